// round 8
// baseline (speedup 1.0000x reference)
#include <cuda_runtime.h>
#include <cuda_bf16.h>
#include <cuda_fp8.h>
#include <cstdint>

typedef unsigned int u32; typedef unsigned long long u64; typedef unsigned short u16;

// ---------------- scratch (__device__ globals; no runtime allocation) --------
__device__ float g_qp[32 * 1024];
__device__ float g_ctx_part[16 * 32 * 1024];
__device__ __align__(16) u16 g_vh[67108864];            // bf16 hi of values
__device__ __align__(16) unsigned char g_a8[67108864];  // e4m3(values)
__device__ __align__(16) unsigned char g_al8[67108864]; // e4m3((values - hi)*512)
__device__ __align__(16) u16 g_w1t_h[1048576];          // bf16 hi of W1^T
__device__ __align__(16) unsigned char g_b8h[1048576];  // e4m3(W1^T * 16)
__device__ __align__(16) unsigned char g_b8l[1048576];  // e4m3((W1^T - hi)*8192)

// ---------------- helpers ----------------------------------------------------
__device__ __forceinline__ u32 smem_u32(const void* p) {
    u32 a;
    asm("{ .reg .u64 t; cvta.to.shared.u64 t, %1; cvt.u32.u64 %0, t; }" : "=r"(a) : "l"(p));
    return a;
}
#define CP_ASYNC(dst, src) \
    asm volatile("cp.async.cg.shared.global [%0], [%1], 16;" :: "r"(dst), "l"(src) : "memory")
#define CP_COMMIT() asm volatile("cp.async.commit_group;" ::: "memory")
#define CP_WAIT(n)  asm volatile("cp.async.wait_group %0;" :: "n"(n) : "memory")

__device__ __forceinline__ void ldsm4(u32 (&r)[4], u32 addr) {
    asm volatile("ldmatrix.sync.aligned.m8n8.x4.shared.b16 {%0,%1,%2,%3}, [%4];"
                 : "=r"(r[0]), "=r"(r[1]), "=r"(r[2]), "=r"(r[3]) : "r"(addr));
}
__device__ __forceinline__ void mma_bf16(float* c, const u32* a, u32 b0, u32 b1) {
    asm volatile(
        "mma.sync.aligned.m16n8k16.row.col.f32.bf16.bf16.f32 "
        "{%0,%1,%2,%3}, {%4,%5,%6,%7}, {%8,%9}, {%0,%1,%2,%3};"
        : "+f"(c[0]), "+f"(c[1]), "+f"(c[2]), "+f"(c[3])
        : "r"(a[0]), "r"(a[1]), "r"(a[2]), "r"(a[3]), "r"(b0), "r"(b1));
}
__device__ __forceinline__ void mma_e4m3(float* c, const u32* a, u32 b0, u32 b1) {
    asm volatile(
        "mma.sync.aligned.m16n8k32.row.col.f32.e4m3.e4m3.f32 "
        "{%0,%1,%2,%3}, {%4,%5,%6,%7}, {%8,%9}, {%0,%1,%2,%3};"
        : "+f"(c[0]), "+f"(c[1]), "+f"(c[2]), "+f"(c[3])
        : "r"(a[0]), "r"(a[1]), "r"(a[2]), "r"(a[3]), "r"(b0), "r"(b1));
}

__device__ __forceinline__ u16 f2bf(float x) { return __bfloat16_as_ushort(__float2bfloat16_rn(x)); }
__device__ __forceinline__ float bf2f(u16 u) { return __bfloat162float(__ushort_as_bfloat16(u)); }
__device__ __forceinline__ u32 f2e4(float x) {
    return (u32)__nv_cvt_float_to_fp8(x, __NV_SATFINITE, __NV_E4M3);
}
__device__ __forceinline__ float tanh_fast(float x) {
    float e = __expf(2.0f * x);
    return 1.0f - __fdividef(2.0f, e + 1.0f);
}

// ---------------- K1: query_proj = query @ W2 --------------------------------
__global__ void qp_kernel(const float* __restrict__ query, const float* __restrict__ W2) {
    __shared__ float sq[1024];
    int hc = blockIdx.x, b = blockIdx.y;
    for (int i = threadIdx.x; i < 1024; i += 256) sq[i] = query[b * 1024 + i];
    __syncthreads();
    int h = hc * 256 + threadIdx.x;
    float acc = 0.f;
#pragma unroll 8
    for (int d = 0; d < 1024; d++) acc += sq[d] * W2[(size_t)d * 1024 + h];
    g_qp[b * 1024 + h] = acc;
}

// ---------------- K2: converts -----------------------------------------------
__global__ void conv_values_kernel(const float* __restrict__ src) {
    u32 i = blockIdx.x * 256u + threadIdx.x;
    float4 x = ((const float4*)src)[i];
    u16 h0 = f2bf(x.x), h1 = f2bf(x.y), h2 = f2bf(x.z), h3 = f2bf(x.w);
    float l0 = x.x - bf2f(h0), l1 = x.y - bf2f(h1);
    float l2 = x.z - bf2f(h2), l3 = x.w - bf2f(h3);
    ((uint2*)g_vh)[i] = make_uint2((u32)h0 | ((u32)h1 << 16), (u32)h2 | ((u32)h3 << 16));
    ((u32*)g_a8)[i]  = f2e4(x.x) | (f2e4(x.y) << 8) | (f2e4(x.z) << 16) | (f2e4(x.w) << 24);
    ((u32*)g_al8)[i] = f2e4(l0 * 512.f) | (f2e4(l1 * 512.f) << 8) |
                       (f2e4(l2 * 512.f) << 16) | (f2e4(l3 * 512.f) << 24);
}

__global__ void conv_w1_kernel(const float* __restrict__ W1) {
    __shared__ float t[32][33];
    int d0 = blockIdx.x * 32, h0 = blockIdx.y * 32;
    int tx = threadIdx.x, ty = threadIdx.y;  // 32 x 8
#pragma unroll
    for (int i = 0; i < 4; i++) {
        int d = ty * 4 + i;
        t[d][tx] = W1[(size_t)(d0 + d) * 1024 + h0 + tx];
    }
    __syncthreads();
#pragma unroll
    for (int i = 0; i < 4; i++) {
        int h = ty * 4 + i;
        float x = t[tx][h];
        u16 hi = f2bf(x);
        float lo = x - bf2f(hi);
        size_t o = (size_t)(h0 + h) * 1024 + d0 + tx;
        g_w1t_h[o] = hi;
        g_b8h[o] = (unsigned char)f2e4(x * 16.f);
        g_b8l[o] = (unsigned char)f2e4(lo * 8192.f);
    }
}

// ---------------- K3: bf16-hi + fp8-lo fused scores --------------------------
// Block 128x128, 256 thr, warp tile 64x32 (2m x 4n), Kc=32, 4-stage pipeline.
// Stage (32KB): AH 8K | A8 4K | AL8 4K | BH 8K | B8H 4K | B8L 4K
#define AH_OFF   0
#define A8_OFF   8192
#define AL8_OFF  12288
#define BH_OFF   16384
#define B8H_OFF  24576
#define B8L_OFF  28672
#define STAGE_B  32768
#define DYN_BYTES (4 * STAGE_B)    // 131072

__device__ __forceinline__ void issue_stage(u32 st, int tid, u32 m0, u32 n0, int kt) {
    const u32 k0 = (u32)kt << 5;
    const u32 r = (u32)tid >> 1;               // 0..127
    const u32 c2 = ((u32)tid & 1) * 2;
    const u32 s = (u32)tid & 1;
    const u32 kbf = (r >> 1) & 3;              // bf16 swizzle key (64B rows)
    const u32 k8 = (r >> 2) & 1;               // fp8 swizzle key (32B rows)
    const size_t rowA = (size_t)(m0 + r) * 1024 + k0;
    const size_t rowB = (size_t)(n0 + r) * 1024 + k0;
#pragma unroll
    for (int i = 0; i < 2; i++) {
        const u32 c = c2 + i;
        const u32 sw = ((c ^ kbf) << 4);
        CP_ASYNC(st + AH_OFF + r * 64 + sw, g_vh + rowA + c * 8);
        CP_ASYNC(st + BH_OFF + r * 64 + sw, g_w1t_h + rowB + c * 8);
    }
    const u32 sw8 = ((s ^ k8) << 4);
    CP_ASYNC(st + A8_OFF  + r * 32 + sw8, g_a8  + rowA + s * 16);
    CP_ASYNC(st + AL8_OFF + r * 32 + sw8, g_al8 + rowA + s * 16);
    CP_ASYNC(st + B8H_OFF + r * 32 + sw8, g_b8h + rowB + s * 16);
    CP_ASYNC(st + B8L_OFF + r * 32 + sw8, g_b8l + rowB + s * 16);
}

__global__ __launch_bounds__(256, 1)
void scores_mma(const float* __restrict__ vvec, float* __restrict__ scores) {
    extern __shared__ __align__(16) char dyn[];
    const u32 dynb = smem_u32(dyn);

    __shared__ float qs[128], vs[128];
    __shared__ float red[4][128];

    const int tid = threadIdx.x;
    const int lane = tid & 31;
    const int wid = tid >> 5;
    const int wm = wid >> 2;         // 2 m-warps (64 rows each)
    const int wn = wid & 3;          // 4 n-warps (32 cols each)
    const u32 m0 = blockIdx.x * 128u;
    const int b = (int)(m0 >> 11);

    // bf16 A: 16-row tiles, 64B rows, 4-seg swizzle
    const u32 rA0 = (u32)(wm * 64 + (lane & 15));
    const u32 keyA = (rA0 >> 1) & 3;
    u32 a_base[4];
#pragma unroll
    for (int tm = 0; tm < 4; tm++) a_base[tm] = (rA0 + (u32)tm * 16u) * 64u;
    u32 aswz[2];
#pragma unroll
    for (int kk = 0; kk < 2; kk++)
        aswz[kk] = ((((u32)(lane >> 4)) + ((u32)kk << 1)) ^ keyA) << 4;

    // bf16 B: rows = n
    const u32 rB0 = (u32)(wn * 32 + ((lane >> 4) << 3) + (lane & 7));
    const u32 keyB = (rB0 >> 1) & 3;
    u32 b_base[2];
#pragma unroll
    for (int g = 0; g < 2; g++) b_base[g] = (rB0 + (u32)g * 16u) * 64u;
    u32 bswz[2];
#pragma unroll
    for (int kk = 0; kk < 2; kk++)
        bswz[kk] = ((((u32)((lane >> 3) & 1)) + ((u32)kk << 1)) ^ keyB) << 4;

    // fp8: 32B rows, 2-seg swizzle key = (row>>2)&1
    const u32 r8A = (u32)(wm * 64 + (lane & 15));
    const u32 s8A = (((u32)(lane >> 4)) ^ ((r8A >> 2) & 1)) << 4;
    u32 a8_base[4];
#pragma unroll
    for (int tm = 0; tm < 4; tm++) a8_base[tm] = (r8A + (u32)tm * 16u) * 32u;
    const u32 r8B = (u32)(wn * 32 + (lane & 15));
    const u32 s8B = (((u32)(lane >> 4)) ^ ((r8B >> 2) & 1)) << 4;
    u32 b8_base[2];
#pragma unroll
    for (int g = 0; g < 2; g++) b8_base[g] = (r8B + (u32)g * 16u) * 32u;

    float srow[8];
#pragma unroll
    for (int i = 0; i < 8; i++) srow[i] = 0.f;

    for (int hc = 0; hc < 8; hc++) {
        const u32 n0 = (u32)hc * 128u;
        __syncthreads();                       // prev epilogue done; stages free
        if (tid < 128) {
            qs[tid] = g_qp[b * 1024 + (int)n0 + tid];
            vs[tid] = vvec[(int)n0 + tid];
        }

        float acc[4][4][4], accl[4][4][4];
#pragma unroll
        for (int tm = 0; tm < 4; tm++)
#pragma unroll
            for (int tn = 0; tn < 4; tn++)
#pragma unroll
                for (int q = 0; q < 4; q++) { acc[tm][tn][q] = 0.f; accl[tm][tn][q] = 0.f; }

        issue_stage(dynb + 0u * STAGE_B, tid, m0, n0, 0); CP_COMMIT();
        issue_stage(dynb + 1u * STAGE_B, tid, m0, n0, 1); CP_COMMIT();
        issue_stage(dynb + 2u * STAGE_B, tid, m0, n0, 2); CP_COMMIT();

        for (int t = 0; t < 32; t++) {
            CP_WAIT(2);
            __syncthreads();
            const u32 base = dynb + (u32)(t & 3) * STAGE_B;

            // ---- fp8 terms (k=32 in one mma) ----
            u32 a8f[4][4], al8f[4][4], b8hf[2][4], b8lf[2][4];
#pragma unroll
            for (int tm = 0; tm < 4; tm++) {
                ldsm4(a8f[tm],  base + A8_OFF  + a8_base[tm] + s8A);
                ldsm4(al8f[tm], base + AL8_OFF + a8_base[tm] + s8A);
            }
#pragma unroll
            for (int g = 0; g < 2; g++) {
                ldsm4(b8hf[g], base + B8H_OFF + b8_base[g] + s8B);
                ldsm4(b8lf[g], base + B8L_OFF + b8_base[g] + s8B);
            }
#pragma unroll
            for (int g = 0; g < 2; g++)
#pragma unroll
                for (int q = 0; q < 2; q++)
#pragma unroll
                    for (int tm = 0; tm < 4; tm++)
                        mma_e4m3(accl[tm][g * 2 + q], al8f[tm], b8hf[g][q], b8hf[g][q + 2]);
#pragma unroll
            for (int g = 0; g < 2; g++)
#pragma unroll
                for (int q = 0; q < 2; q++)
#pragma unroll
                    for (int tm = 0; tm < 4; tm++)
                        mma_e4m3(accl[tm][g * 2 + q], a8f[tm], b8lf[g][q], b8lf[g][q + 2]);

            // ---- bf16 main term (2 x k16) ----
#pragma unroll
            for (int kk = 0; kk < 2; kk++) {
                u32 ah[4][4], bh[2][4];
#pragma unroll
                for (int tm = 0; tm < 4; tm++)
                    ldsm4(ah[tm], base + AH_OFF + a_base[tm] + aswz[kk]);
#pragma unroll
                for (int g = 0; g < 2; g++)
                    ldsm4(bh[g], base + BH_OFF + b_base[g] + bswz[kk]);
#pragma unroll
                for (int g = 0; g < 2; g++)
#pragma unroll
                    for (int q = 0; q < 2; q++)
#pragma unroll
                        for (int tm = 0; tm < 4; tm++)
                            mma_bf16(acc[tm][g * 2 + q], ah[tm], bh[g][q * 2], bh[g][q * 2 + 1]);
            }

            if (t + 3 < 32) issue_stage(dynb + (u32)((t + 3) & 3) * STAGE_B, tid, m0, n0, t + 3);
            CP_COMMIT();
        }

        // epilogue: tanh(acc_hi + acc_lo/8192 + qp) * v
        const float LO = 1.220703125e-4f;   // 2^-13
#pragma unroll
        for (int tm = 0; tm < 4; tm++)
#pragma unroll
            for (int tn = 0; tn < 4; tn++) {
                const int c0 = wn * 32 + tn * 8 + (lane & 3) * 2;
                const float q0 = qs[c0], q1 = qs[c0 + 1];
                const float v0 = vs[c0], v1 = vs[c0 + 1];
                float e0 = acc[tm][tn][0] + LO * accl[tm][tn][0] + q0;
                float e1 = acc[tm][tn][1] + LO * accl[tm][tn][1] + q1;
                float e2 = acc[tm][tn][2] + LO * accl[tm][tn][2] + q0;
                float e3 = acc[tm][tn][3] + LO * accl[tm][tn][3] + q1;
                srow[tm * 2 + 0] += tanh_fast(e0) * v0 + tanh_fast(e1) * v1;
                srow[tm * 2 + 1] += tanh_fast(e2) * v0 + tanh_fast(e3) * v1;
            }
    }

    // quad reduce (deterministic) then across the 4 n-warp groups
#pragma unroll
    for (int i = 0; i < 8; i++) {
        srow[i] += __shfl_xor_sync(0xffffffffu, srow[i], 1);
        srow[i] += __shfl_xor_sync(0xffffffffu, srow[i], 2);
    }
    __syncthreads();
    if ((lane & 3) == 0) {
#pragma unroll
        for (int tm = 0; tm < 4; tm++) {
            const int r = wm * 64 + tm * 16 + (lane >> 2);
            red[wn][r] = srow[tm * 2];
            red[wn][r + 8] = srow[tm * 2 + 1];
        }
    }
    __syncthreads();
    if (tid < 128)
        scores[m0 + tid] = (red[0][tid] + red[1][tid]) + (red[2][tid] + red[3][tid]);
}

// ---------------- K4: softmax over S -----------------------------------------
__global__ void softmax_kernel(float* __restrict__ w) {
    int b = blockIdx.x;
    float* p = w + b * 2048;
    int t = threadIdx.x;
    __shared__ float sm[32];
    float a0 = p[t], a1 = p[t + 1024];
    float m = fmaxf(a0, a1);
#pragma unroll
    for (int o = 16; o; o >>= 1) m = fmaxf(m, __shfl_xor_sync(0xffffffffu, m, o));
    if ((t & 31) == 0) sm[t >> 5] = m;
    __syncthreads();
    if (t < 32) {
        float mm = sm[t];
#pragma unroll
        for (int o = 16; o; o >>= 1) mm = fmaxf(mm, __shfl_xor_sync(0xffffffffu, mm, o));
        sm[t] = mm;
    }
    __syncthreads();
    m = sm[0];
    __syncthreads();
    float e0 = __expf(a0 - m), e1 = __expf(a1 - m);
    float s = e0 + e1;
#pragma unroll
    for (int o = 16; o; o >>= 1) s += __shfl_xor_sync(0xffffffffu, s, o);
    if ((t & 31) == 0) sm[t >> 5] = s;
    __syncthreads();
    if (t < 32) {
        float ss = sm[t];
#pragma unroll
        for (int o = 16; o; o >>= 1) ss += __shfl_xor_sync(0xffffffffu, ss, o);
        sm[t] = ss;
    }
    __syncthreads();
    float inv = 1.0f / sm[0];
    p[t] = e0 * inv;
    p[t + 1024] = e1 * inv;
}

// ---------------- K5/K6: context = w @ values --------------------------------
__global__ void ctx_part_kernel(const float* __restrict__ values, const float* __restrict__ w) {
    int b = blockIdx.x, j = blockIdx.y;
    __shared__ float ws[128];
    int t = threadIdx.x;
    if (t < 128) ws[t] = w[b * 2048 + j * 128 + t];
    __syncthreads();
    const float* V = values + ((size_t)(b * 2048 + j * 128)) * 1024 + t * 4;
    float4 acc = make_float4(0.f, 0.f, 0.f, 0.f);
#pragma unroll 8
    for (int s = 0; s < 128; s++) {
        float4 x = *(const float4*)(V + (size_t)s * 1024);
        float c = ws[s];
        acc.x += c * x.x; acc.y += c * x.y; acc.z += c * x.z; acc.w += c * x.w;
    }
    *(float4*)&g_ctx_part[((size_t)j * 32 + b) * 1024 + t * 4] = acc;
}

__global__ void ctx_reduce_kernel(float* __restrict__ ctx) {
    int b = blockIdx.x, t = threadIdx.x;
    float4 acc = make_float4(0.f, 0.f, 0.f, 0.f);
#pragma unroll
    for (int j = 0; j < 16; j++) {
        float4 x = *(const float4*)&g_ctx_part[((size_t)j * 32 + b) * 1024 + t * 4];
        acc.x += x.x; acc.y += x.y; acc.z += x.z; acc.w += x.w;
    }
    *(float4*)(ctx + b * 1024 + t * 4) = acc;
}

// ---------------- launch ------------------------------------------------------
extern "C" void kernel_launch(void* const* d_in, const int* in_sizes, int n_in,
                              void* d_out, int out_size) {
    const float* query  = (const float*)d_in[0];
    const float* values = (const float*)d_in[1];
    const float* W1     = (const float*)d_in[2];
    const float* W2     = (const float*)d_in[3];
    const float* v      = (const float*)d_in[4];

    float* ctx     = (float*)d_out;
    float* weights = (float*)d_out + 32 * 1024;

    cudaFuncSetAttribute(scores_mma, cudaFuncAttributeMaxDynamicSharedMemorySize, DYN_BYTES);

    qp_kernel<<<dim3(4, 32), 256>>>(query, W2);
    conv_values_kernel<<<65536, 256>>>(values);
    conv_w1_kernel<<<dim3(32, 32), dim3(32, 8)>>>(W1);
    scores_mma<<<512, 256, DYN_BYTES>>>(v, weights);
    softmax_kernel<<<32, 1024>>>(weights);
    ctx_part_kernel<<<dim3(32, 16), 256>>>(values, weights);
    ctx_reduce_kernel<<<32, 256>>>(ctx);
}

// round 9
// speedup vs baseline: 1.6647x; 1.6647x over previous
#include <cuda_runtime.h>
#include <cuda_bf16.h>
#include <cstdint>

typedef unsigned int u32; typedef unsigned long long u64; typedef unsigned short u16;

// ---------------- scratch (__device__ globals; no runtime allocation) --------
__device__ float g_qp[32 * 1024];
__device__ float g_spart[4 * 65536];             // partial scores [hc][row]
__device__ float g_ctx_part[16 * 32 * 1024];
__device__ __align__(16) u16 g_vh[67108864];     // values hi bf16 [65536][1024]
__device__ __align__(16) u16 g_vl[67108864];     // values lo bf16
__device__ __align__(16) u16 g_w1t_h[1048576];   // W1^T hi bf16 [H][D]
__device__ __align__(16) u16 g_w1t_l[1048576];   // W1^T lo bf16

// ---------------- helpers ----------------------------------------------------
__device__ __forceinline__ u32 smem_u32(const void* p) {
    u32 a;
    asm("{ .reg .u64 t; cvta.to.shared.u64 t, %1; cvt.u32.u64 %0, t; }" : "=r"(a) : "l"(p));
    return a;
}
#define CP_ASYNC(dst, src) \
    asm volatile("cp.async.cg.shared.global [%0], [%1], 16;" :: "r"(dst), "l"(src) : "memory")
#define CP_COMMIT() asm volatile("cp.async.commit_group;" ::: "memory")
#define CP_WAIT(n)  asm volatile("cp.async.wait_group %0;" :: "n"(n) : "memory")

__device__ __forceinline__ void ldsm4(u32 (&r)[4], u32 addr) {
    asm volatile("ldmatrix.sync.aligned.m8n8.x4.shared.b16 {%0,%1,%2,%3}, [%4];"
                 : "=r"(r[0]), "=r"(r[1]), "=r"(r[2]), "=r"(r[3]) : "r"(addr));
}
__device__ __forceinline__ void mma16816(float* c, const u32* a, const u32* b) {
    asm volatile(
        "mma.sync.aligned.m16n8k16.row.col.f32.bf16.bf16.f32 "
        "{%0,%1,%2,%3}, {%4,%5,%6,%7}, {%8,%9}, {%0,%1,%2,%3};"
        : "+f"(c[0]), "+f"(c[1]), "+f"(c[2]), "+f"(c[3])
        : "r"(a[0]), "r"(a[1]), "r"(a[2]), "r"(a[3]), "r"(b[0]), "r"(b[1]));
}

__device__ __forceinline__ u16 f2bf(float x) { return __bfloat16_as_ushort(__float2bfloat16_rn(x)); }
__device__ __forceinline__ float bf2f(u16 u) { return __bfloat162float(__ushort_as_bfloat16(u)); }
__device__ __forceinline__ float tanh_fast(float x) {
    float e = __expf(2.0f * x);
    return 1.0f - __fdividef(2.0f, e + 1.0f);
}

// ---------------- K1: query_proj = query @ W2 --------------------------------
__global__ void qp_kernel(const float* __restrict__ query, const float* __restrict__ W2) {
    __shared__ float sq[1024];
    int hc = blockIdx.x, b = blockIdx.y;
    for (int i = threadIdx.x; i < 1024; i += 256) sq[i] = query[b * 1024 + i];
    __syncthreads();
    int h = hc * 256 + threadIdx.x;
    float acc = 0.f;
#pragma unroll 8
    for (int d = 0; d < 1024; d++) acc += sq[d] * W2[(size_t)d * 1024 + h];
    g_qp[b * 1024 + h] = acc;
}

// ---------------- K2: fp32 -> bf16 hi/lo converts ----------------------------
__global__ void conv_values_kernel(const float* __restrict__ src) {
    u32 i = blockIdx.x * 256u + threadIdx.x;
    float4 x = ((const float4*)src)[i];
    u16 h0 = f2bf(x.x), h1 = f2bf(x.y), h2 = f2bf(x.z), h3 = f2bf(x.w);
    u16 l0 = f2bf(x.x - bf2f(h0)), l1 = f2bf(x.y - bf2f(h1));
    u16 l2 = f2bf(x.z - bf2f(h2)), l3 = f2bf(x.w - bf2f(h3));
    ((uint2*)g_vh)[i] = make_uint2((u32)h0 | ((u32)h1 << 16), (u32)h2 | ((u32)h3 << 16));
    ((uint2*)g_vl)[i] = make_uint2((u32)l0 | ((u32)l1 << 16), (u32)l2 | ((u32)l3 << 16));
}

__global__ void conv_w1_kernel(const float* __restrict__ W1) {
    __shared__ float t[32][33];
    int d0 = blockIdx.x * 32, h0 = blockIdx.y * 32;
    int tx = threadIdx.x, ty = threadIdx.y;  // 32 x 8
#pragma unroll
    for (int i = 0; i < 4; i++) {
        int d = ty * 4 + i;
        t[d][tx] = W1[(size_t)(d0 + d) * 1024 + h0 + tx];
    }
    __syncthreads();
#pragma unroll
    for (int i = 0; i < 4; i++) {
        int h = ty * 4 + i;
        float x = t[tx][h];
        u16 hi = f2bf(x);
        u16 lo = f2bf(x - bf2f(hi));
        g_w1t_h[(size_t)(h0 + h) * 1024 + d0 + tx] = hi;
        g_w1t_l[(size_t)(h0 + h) * 1024 + d0 + tx] = lo;
    }
}

// ---------------- K3: persistent mma.sync fused scores -----------------------
// 2048 units = 512 M-tiles x 4 H-chunks. Unit: M=128, N=256, K=1024, 32 stages.
// 148 persistent CTAs, continuous 4-stage cp.async pipeline across units.
#define AH_OFF   0
#define AL_OFF   8192
#define BH_OFF   16384
#define BL_OFF   32768
#define STAGE_B  49152
#define DYN_BYTES (4 * STAGE_B)    // 196608
#define NCTA     148
#define NUNITS   2048

__device__ __forceinline__ void issue_stage(u32 sstage, int tid, u32 m0, u32 n0, u32 kt) {
    const u32 k0 = kt << 5;
    const u32 r = (u32)tid >> 2, c = (u32)tid & 3;
    const u32 swz = (c ^ ((r >> 1) & 3)) << 4;
    const u32 dstA = sstage + r * 64 + swz;
    const size_t soA = (size_t)(m0 + r) * 1024 + k0 + c * 8;
    CP_ASYNC(dstA + AH_OFF, g_vh + soA);
    CP_ASYNC(dstA + AL_OFF, g_vl + soA);
#pragma unroll
    for (int j = 0; j < 2; j++) {
        const u32 rb = r + (u32)j * 128u;          // (rb>>1)&3 == (r>>1)&3
        const u32 dstB = sstage + BH_OFF + rb * 64 + swz;
        const size_t soB = (size_t)(n0 + rb) * 1024 + k0 + c * 8;
        CP_ASYNC(dstB, g_w1t_h + soB);
        CP_ASYNC(dstB + (BL_OFF - BH_OFF), g_w1t_l + soB);
    }
}

__global__ __launch_bounds__(512, 1)
void scores_mma(const float* __restrict__ vvec) {
    extern __shared__ __align__(16) char dyn[];
    const u32 dynb = smem_u32(dyn);

    __shared__ float qs[256], vs[256];
    __shared__ float red[4][128];

    const int tid = threadIdx.x;
    const int lane = tid & 31;
    const int wid = tid >> 5;
    const int wm = wid & 3;          // 4 m-warps (32 rows each)
    const int wn = wid >> 2;         // 4 n-warps (64 cols each)
    const int bx = blockIdx.x;

    // per-thread ldmatrix offsets (swizzle keys invariant under tm/nh/p shifts)
    const u32 rA0 = (u32)(wm * 32 + (lane & 15));
    const u32 keyA = (rA0 >> 1) & 3;
    u32 a_base[2], aswz[2];
#pragma unroll
    for (int tm = 0; tm < 2; tm++) a_base[tm] = (rA0 + (u32)tm * 16u) * 64u;
#pragma unroll
    for (int kk = 0; kk < 2; kk++)
        aswz[kk] = (((u32)(lane >> 4) | ((u32)kk << 1)) ^ keyA) << 4;

    const u32 rB0 = (u32)(wn * 64 + ((lane >> 4) << 3) + (lane & 7));
    const u32 keyB = (rB0 >> 1) & 3;
    u32 b_base[2][2], bswz[2];
#pragma unroll
    for (int nh = 0; nh < 2; nh++)
#pragma unroll
        for (int p = 0; p < 2; p++)
            b_base[nh][p] = (rB0 + (u32)(nh * 32 + p * 16)) * 64u;
#pragma unroll
    for (int kk = 0; kk < 2; kk++)
        bswz[kk] = (((u32)((lane >> 3) & 1) | ((u32)kk << 1)) ^ keyB) << 4;

    const int nunits = (NUNITS - bx + NCTA - 1) / NCTA;
    const int total = nunits * 32;

    // prologue: prefetch stages 0..2
#pragma unroll
    for (int p = 0; p < 3; p++) {
        const int u = bx + (p >> 5) * NCTA;        // p<32 so always unit 0
        const u32 m0p = (u32)(u >> 2) * 128u;
        const u32 n0p = (u32)(u & 3) * 256u;
        issue_stage(dynb + (u32)(p & 3) * STAGE_B, tid, m0p, n0p, (u32)(p & 31));
        CP_COMMIT();
    }

    float acc[2][8][4];
#pragma unroll
    for (int tm = 0; tm < 2; tm++)
#pragma unroll
        for (int tn = 0; tn < 8; tn++)
#pragma unroll
            for (int q = 0; q < 4; q++) acc[tm][tn][q] = 0.f;

    for (int ls = 0; ls < total; ls++) {
        CP_WAIT(2);
        __syncthreads();
        const u32 base = dynb + (u32)(ls & 3) * STAGE_B;
#pragma unroll
        for (int kk = 0; kk < 2; kk++) {
            u32 ah[2][4], al[2][4];
#pragma unroll
            for (int tm = 0; tm < 2; tm++) {
                ldsm4(ah[tm], base + AH_OFF + a_base[tm] + aswz[kk]);
                ldsm4(al[tm], base + AL_OFF + a_base[tm] + aswz[kk]);
            }
#pragma unroll
            for (int nh = 0; nh < 2; nh++) {
                u32 bh[2][4], bl[2][4];
#pragma unroll
                for (int p = 0; p < 2; p++) {
                    ldsm4(bh[p], base + BH_OFF + b_base[nh][p] + bswz[kk]);
                    ldsm4(bl[p], base + BL_OFF + b_base[nh][p] + bswz[kk]);
                }
#pragma unroll
                for (int p = 0; p < 2; p++)
#pragma unroll
                    for (int q = 0; q < 2; q++) {
                        const int tn = nh * 4 + p * 2 + q;
#pragma unroll
                        for (int tm = 0; tm < 2; tm++) {
                            mma16816(acc[tm][tn], ah[tm], &bh[p][q * 2]);
                            mma16816(acc[tm][tn], al[tm], &bh[p][q * 2]);
                            mma16816(acc[tm][tn], ah[tm], &bl[p][q * 2]);
                        }
                    }
            }
        }
        // prefetch stage ls+3 (crosses unit boundaries seamlessly)
        {
            const int pf = ls + 3;
            if (pf < total) {
                const int u = bx + (pf >> 5) * NCTA;
                const u32 m0p = (u32)(u >> 2) * 128u;
                const u32 n0p = (u32)(u & 3) * 256u;
                issue_stage(dynb + (u32)(pf & 3) * STAGE_B, tid, m0p, n0p, (u32)(pf & 31));
            }
            CP_COMMIT();
        }

        if ((ls & 31) == 31) {               // unit complete -> epilogue
            const int u = bx + (ls >> 5) * NCTA;
            const u32 m0 = (u32)(u >> 2) * 128u;
            const int hc = u & 3;
            const int b = (int)(m0 >> 11);
            __syncthreads();
            if (tid < 256) {
                qs[tid] = g_qp[b * 1024 + hc * 256 + tid];
                vs[tid] = vvec[hc * 256 + tid];
            }
            __syncthreads();

            float srow[4] = {0.f, 0.f, 0.f, 0.f};
#pragma unroll
            for (int tm = 0; tm < 2; tm++)
#pragma unroll
                for (int tn = 0; tn < 8; tn++) {
                    const int c0 = wn * 64 + tn * 8 + (lane & 3) * 2;
                    const float q0 = qs[c0], q1 = qs[c0 + 1];
                    const float v0 = vs[c0], v1 = vs[c0 + 1];
                    srow[tm * 2 + 0] += tanh_fast(acc[tm][tn][0] + q0) * v0 +
                                        tanh_fast(acc[tm][tn][1] + q1) * v1;
                    srow[tm * 2 + 1] += tanh_fast(acc[tm][tn][2] + q0) * v0 +
                                        tanh_fast(acc[tm][tn][3] + q1) * v1;
                    acc[tm][tn][0] = 0.f; acc[tm][tn][1] = 0.f;
                    acc[tm][tn][2] = 0.f; acc[tm][tn][3] = 0.f;
                }
#pragma unroll
            for (int i = 0; i < 4; i++) {
                srow[i] += __shfl_xor_sync(0xffffffffu, srow[i], 1);
                srow[i] += __shfl_xor_sync(0xffffffffu, srow[i], 2);
            }
            if ((lane & 3) == 0) {
                const int r0 = wm * 32 + (lane >> 2);
                red[wn][r0]      = srow[0];
                red[wn][r0 + 8]  = srow[1];
                red[wn][r0 + 16] = srow[2];
                red[wn][r0 + 24] = srow[3];
            }
            __syncthreads();
            if (tid < 128)
                g_spart[hc * 65536 + (int)m0 + tid] =
                    (red[0][tid] + red[1][tid]) + (red[2][tid] + red[3][tid]);
        }
    }
}

// ---------------- K4: softmax over S (sums 4 hc-partials) --------------------
__global__ void softmax_kernel(float* __restrict__ w) {
    int b = blockIdx.x;
    float* p = w + b * 2048;
    int t = threadIdx.x;
    __shared__ float sm[32];
    const int r0 = b * 2048 + t;
    float a0 = ((g_spart[r0] + g_spart[65536 + r0]) +
                (g_spart[131072 + r0] + g_spart[196608 + r0]));
    float a1 = ((g_spart[r0 + 1024] + g_spart[65536 + r0 + 1024]) +
                (g_spart[131072 + r0 + 1024] + g_spart[196608 + r0 + 1024]));
    float m = fmaxf(a0, a1);
#pragma unroll
    for (int o = 16; o; o >>= 1) m = fmaxf(m, __shfl_xor_sync(0xffffffffu, m, o));
    if ((t & 31) == 0) sm[t >> 5] = m;
    __syncthreads();
    if (t < 32) {
        float mm = sm[t];
#pragma unroll
        for (int o = 16; o; o >>= 1) mm = fmaxf(mm, __shfl_xor_sync(0xffffffffu, mm, o));
        sm[t] = mm;
    }
    __syncthreads();
    m = sm[0];
    __syncthreads();
    float e0 = __expf(a0 - m), e1 = __expf(a1 - m);
    float s = e0 + e1;
#pragma unroll
    for (int o = 16; o; o >>= 1) s += __shfl_xor_sync(0xffffffffu, s, o);
    if ((t & 31) == 0) sm[t >> 5] = s;
    __syncthreads();
    if (t < 32) {
        float ss = sm[t];
#pragma unroll
        for (int o = 16; o; o >>= 1) ss += __shfl_xor_sync(0xffffffffu, ss, o);
        sm[t] = ss;
    }
    __syncthreads();
    float inv = 1.0f / sm[0];
    p[t] = e0 * inv;
    p[t + 1024] = e1 * inv;
}

// ---------------- K5/K6: context = w @ values --------------------------------
__global__ void ctx_part_kernel(const float* __restrict__ values, const float* __restrict__ w) {
    int b = blockIdx.x, j = blockIdx.y;
    __shared__ float ws[128];
    int t = threadIdx.x;
    if (t < 128) ws[t] = w[b * 2048 + j * 128 + t];
    __syncthreads();
    const float* V = values + ((size_t)(b * 2048 + j * 128)) * 1024 + t * 4;
    float4 acc = make_float4(0.f, 0.f, 0.f, 0.f);
#pragma unroll 8
    for (int s = 0; s < 128; s++) {
        float4 x = *(const float4*)(V + (size_t)s * 1024);
        float c = ws[s];
        acc.x += c * x.x; acc.y += c * x.y; acc.z += c * x.z; acc.w += c * x.w;
    }
    *(float4*)&g_ctx_part[((size_t)j * 32 + b) * 1024 + t * 4] = acc;
}

__global__ void ctx_reduce_kernel(float* __restrict__ ctx) {
    int b = blockIdx.x, t = threadIdx.x;
    float4 acc = make_float4(0.f, 0.f, 0.f, 0.f);
#pragma unroll
    for (int j = 0; j < 16; j++) {
        float4 x = *(const float4*)&g_ctx_part[((size_t)j * 32 + b) * 1024 + t * 4];
        acc.x += x.x; acc.y += x.y; acc.z += x.z; acc.w += x.w;
    }
    *(float4*)(ctx + b * 1024 + t * 4) = acc;
}

// ---------------- launch ------------------------------------------------------
extern "C" void kernel_launch(void* const* d_in, const int* in_sizes, int n_in,
                              void* d_out, int out_size) {
    const float* query  = (const float*)d_in[0];
    const float* values = (const float*)d_in[1];
    const float* W1     = (const float*)d_in[2];
    const float* W2     = (const float*)d_in[3];
    const float* v      = (const float*)d_in[4];

    float* ctx     = (float*)d_out;
    float* weights = (float*)d_out + 32 * 1024;

    cudaFuncSetAttribute(scores_mma, cudaFuncAttributeMaxDynamicSharedMemorySize, DYN_BYTES);

    qp_kernel<<<dim3(4, 32), 256>>>(query, W2);
    conv_values_kernel<<<65536, 256>>>(values);
    conv_w1_kernel<<<dim3(32, 32), dim3(32, 8)>>>(W1);
    scores_mma<<<NCTA, 512, DYN_BYTES>>>(v);
    softmax_kernel<<<32, 1024>>>(weights);
    ctx_part_kernel<<<dim3(32, 16), 256>>>(values, weights);
    ctx_reduce_kernel<<<32, 256>>>(ctx);
}